// round 1
// baseline (speedup 1.0000x reference)
#include <cuda_runtime.h>
#include <cstdint>

// Problem shape (fixed by the dataset)
#define NMAX 100000
#define EMAX 1600000
#define INC 128
#define HIDC 128
#define OUTC 64

// ---------------- scratch (no allocation allowed) ----------------
__device__ float g_h1[(size_t)NMAX * HIDC];   // (x@W1)*dinv
__device__ float g_hr[(size_t)NMAX * HIDC];   // relu(agg1 + b1)
__device__ float g_h2[(size_t)NMAX * OUTC];   // (hr@W2)*dinv
__device__ float g_dinv[NMAX];
__device__ int   g_cnt_in[NMAX];
__device__ int   g_cnt_out[NMAX];
__device__ int   g_rowstart[NMAX];
__device__ int   g_cursor[NMAX];
__device__ int   g_bsum[1024];
__device__ int   g_csr[EMAX];

// ---------------- CSR build ----------------
__global__ void zero_kernel(int n) {
    int i = blockIdx.x * blockDim.x + threadIdx.x;
    if (i < n) { g_cnt_in[i] = 0; g_cnt_out[i] = 0; }
}

__global__ void hist_kernel(const int* __restrict__ ei, int E) {
    int e = blockIdx.x * blockDim.x + threadIdx.x;
    if (e < E) {
        atomicAdd(&g_cnt_out[ei[e]], 1);      // src -> out-degree (normalization)
        atomicAdd(&g_cnt_in[ei[E + e]], 1);   // dst -> in-degree (CSR)
    }
}

// block-wise inclusive scan -> exclusive per-block results + block sums
__global__ void scan_block_kernel(int n) {
    __shared__ int sm[1024];
    int t = threadIdx.x;
    int gid = blockIdx.x * 1024 + t;
    int v = (gid < n) ? g_cnt_in[gid] : 0;
    sm[t] = v;
    __syncthreads();
    #pragma unroll
    for (int off = 1; off < 1024; off <<= 1) {
        int add = (t >= off) ? sm[t - off] : 0;
        __syncthreads();
        sm[t] += add;
        __syncthreads();
    }
    if (gid < n) g_rowstart[gid] = sm[t] - v;  // exclusive within block
    if (t == 1023) g_bsum[blockIdx.x] = sm[1023];
}

__global__ void scan_sums_kernel(int nb) {
    if (threadIdx.x == 0 && blockIdx.x == 0) {
        int acc = 0;
        for (int i = 0; i < nb; i++) { int v = g_bsum[i]; g_bsum[i] = acc; acc += v; }
    }
}

// add block offsets, init cursor, compute deg_inv
__global__ void scan_finish_kernel(int n) {
    int i = blockIdx.x * 1024 + threadIdx.x;
    if (i < n) {
        int v = g_rowstart[i] + g_bsum[blockIdx.x];
        g_rowstart[i] = v;
        g_cursor[i] = v;
        int d = g_cnt_out[i];
        g_dinv[i] = 1.0f / (float)(d > 1 ? d : 1);
    }
}

__global__ void scatter_kernel(const int* __restrict__ ei, int E) {
    int e = blockIdx.x * blockDim.x + threadIdx.x;
    if (e < E) {
        int d = ei[E + e];
        int pos = atomicAdd(&g_cursor[d], 1);
        g_csr[pos] = ei[e];  // store source node id grouped by dst
    }
}

// ---------------- SGEMM: out[M,BN] = (A[M,128] @ W[128,BN]) * dinv[row] ----------------
template <int BN, bool FIRST>
__global__ __launch_bounds__(256)
void gemm_kernel(const float* __restrict__ Ain, const float* __restrict__ W, int M) {
    constexpr int BM = 64, BK = 32, TM = 4, TN = BN / 16;
    const float* __restrict__ A = FIRST ? Ain : g_hr;
    float* __restrict__ out = FIRST ? g_h1 : g_h2;

    __shared__ float As[BM][BK];
    __shared__ float Ws[BK][BN];

    int tid = threadIdx.x;        // 256 threads
    int tx = tid & 15;            // col group 0..15
    int ty = tid >> 4;            // row group 0..15
    int row0 = blockIdx.x * BM;

    float acc[TM][TN];
    #pragma unroll
    for (int i = 0; i < TM; i++)
        #pragma unroll
        for (int j = 0; j < TN; j++) acc[i][j] = 0.0f;

    for (int kc = 0; kc < 128; kc += BK) {
        // A tile: 64x32 floats = 512 float4, 2 per thread
        #pragma unroll
        for (int i = 0; i < 2; i++) {
            int idx = tid + i * 256;
            int r = idx >> 3, q = idx & 7;
            float4 v = make_float4(0.f, 0.f, 0.f, 0.f);
            int gr = row0 + r;
            if (gr < M) v = *(const float4*)(A + (size_t)gr * 128 + kc + q * 4);
            *(float4*)&As[r][q * 4] = v;
        }
        // W tile: 32 x BN floats
        constexpr int WV = (BK * BN / 4) / 256;
        #pragma unroll
        for (int i = 0; i < WV; i++) {
            int idx = tid + i * 256;
            int k = idx / (BN / 4);
            int c4 = idx % (BN / 4);
            *(float4*)&Ws[k][c4 * 4] = *(const float4*)(W + (size_t)(kc + k) * BN + c4 * 4);
        }
        __syncthreads();

        #pragma unroll
        for (int k = 0; k < BK; k++) {
            float a[TM], b[TN];
            #pragma unroll
            for (int i = 0; i < TM; i++) a[i] = As[ty * TM + i][k];
            #pragma unroll
            for (int j = 0; j < TN / 4; j++)
                *(float4*)&b[j * 4] = *(const float4*)&Ws[k][tx * TN + j * 4];
            #pragma unroll
            for (int i = 0; i < TM; i++)
                #pragma unroll
                for (int j = 0; j < TN; j++) acc[i][j] += a[i] * b[j];
        }
        __syncthreads();
    }

    #pragma unroll
    for (int i = 0; i < TM; i++) {
        int gr = row0 + ty * TM + i;
        if (gr < M) {
            float s = g_dinv[gr];
            #pragma unroll
            for (int j = 0; j < TN / 4; j++) {
                float4 v;
                v.x = acc[i][j * 4 + 0] * s;
                v.y = acc[i][j * 4 + 1] * s;
                v.z = acc[i][j * 4 + 2] * s;
                v.w = acc[i][j * 4 + 3] * s;
                *(float4*)(out + (size_t)gr * BN + tx * TN + j * 4) = v;
            }
        }
    }
}

// ---------------- aggregation: warp per dst node, CSR gather-sum ----------------
template <int C, bool FIRST>
__global__ void agg_kernel(const float* __restrict__ bias, float* __restrict__ outp, int n) {
    int gw = (blockIdx.x * blockDim.x + threadIdx.x) >> 5;
    int lane = threadIdx.x & 31;
    if (gw >= n) return;

    const float* __restrict__ h = FIRST ? g_h1 : g_h2;
    float* __restrict__ out = FIRST ? g_hr : outp;

    int beg = g_rowstart[gw];
    int m = g_cnt_in[gw];

    if constexpr (C == 128) {
        size_t off = (size_t)lane * 4;
        float4 acc = make_float4(0.f, 0.f, 0.f, 0.f);
        int e = 0;
        for (; e + 2 <= m; e += 2) {
            int s0 = g_csr[beg + e];
            int s1 = g_csr[beg + e + 1];
            float4 a = *(const float4*)(h + (size_t)s0 * C + off);
            float4 b = *(const float4*)(h + (size_t)s1 * C + off);
            acc.x += a.x + b.x; acc.y += a.y + b.y;
            acc.z += a.z + b.z; acc.w += a.w + b.w;
        }
        if (e < m) {
            int s = g_csr[beg + e];
            float4 a = *(const float4*)(h + (size_t)s * C + off);
            acc.x += a.x; acc.y += a.y; acc.z += a.z; acc.w += a.w;
        }
        float4 bb = *(const float4*)(bias + lane * 4);
        acc.x += bb.x; acc.y += bb.y; acc.z += bb.z; acc.w += bb.w;
        if (FIRST) {
            acc.x = fmaxf(acc.x, 0.f); acc.y = fmaxf(acc.y, 0.f);
            acc.z = fmaxf(acc.z, 0.f); acc.w = fmaxf(acc.w, 0.f);
        }
        *(float4*)(out + (size_t)gw * C + off) = acc;
    } else {
        size_t off = (size_t)lane * 2;
        float2 acc = make_float2(0.f, 0.f);
        int e = 0;
        for (; e + 2 <= m; e += 2) {
            int s0 = g_csr[beg + e];
            int s1 = g_csr[beg + e + 1];
            float2 a = *(const float2*)(h + (size_t)s0 * C + off);
            float2 b = *(const float2*)(h + (size_t)s1 * C + off);
            acc.x += a.x + b.x; acc.y += a.y + b.y;
        }
        if (e < m) {
            int s = g_csr[beg + e];
            float2 a = *(const float2*)(h + (size_t)s * C + off);
            acc.x += a.x; acc.y += a.y;
        }
        float2 bb = *(const float2*)(bias + lane * 2);
        acc.x += bb.x; acc.y += bb.y;
        if (FIRST) { acc.x = fmaxf(acc.x, 0.f); acc.y = fmaxf(acc.y, 0.f); }
        *(float2*)(out + (size_t)gw * C + off) = acc;
    }
}

// ---------------- launch ----------------
extern "C" void kernel_launch(void* const* d_in, const int* in_sizes, int n_in,
                              void* d_out, int out_size) {
    const float* x  = (const float*)d_in[0];
    const int*   ei = (const int*)d_in[1];
    const float* W1 = (const float*)d_in[2];
    const float* b1 = (const float*)d_in[3];
    const float* W2 = (const float*)d_in[4];
    const float* b2 = (const float*)d_in[5];
    float* out = (float*)d_out;

    int N = in_sizes[0] / INC;   // 100000
    int E = in_sizes[1] / 2;     // 1600000

    int nb1k = (N + 1023) / 1024;

    zero_kernel<<<(N + 255) / 256, 256>>>(N);
    hist_kernel<<<(E + 255) / 256, 256>>>(ei, E);
    scan_block_kernel<<<nb1k, 1024>>>(N);
    scan_sums_kernel<<<1, 32>>>(nb1k);
    scan_finish_kernel<<<nb1k, 1024>>>(N);
    scatter_kernel<<<(E + 255) / 256, 256>>>(ei, E);

    // layer 1
    gemm_kernel<HIDC, true><<<(N + 63) / 64, 256>>>(x, W1, N);
    agg_kernel<HIDC, true><<<(N * 32 + 255) / 256, 256>>>(b1, nullptr, N);

    // layer 2
    gemm_kernel<OUTC, false><<<(N + 63) / 64, 256>>>(nullptr, W2, N);
    agg_kernel<OUTC, false><<<(N * 32 + 255) / 256, 256>>>(b2, out, N);
}

// round 3
// speedup vs baseline: 1.4501x; 1.4501x over previous
#include <cuda_runtime.h>
#include <cstdint>

// Problem shape (fixed by the dataset)
#define NMAX 100000
#define EMAX 1600000
#define INC 128
#define HIDC 128
#define OUTC 64

// ---------------- scratch (no allocation allowed) ----------------
__device__ float g_h1[(size_t)NMAX * HIDC];   // (x@W1)*dinv
__device__ float g_hr[(size_t)NMAX * HIDC];   // relu(agg1 + b1)
__device__ float g_h2[(size_t)NMAX * OUTC];   // (hr@W2)*dinv
__device__ float g_dinv[NMAX];
__device__ int   g_cnt_in[NMAX];
__device__ int   g_cnt_out[NMAX];
__device__ int   g_rowstart[NMAX];
__device__ int   g_cursor[NMAX];
__device__ int   g_bsum[1024];
__device__ int   g_csr[EMAX];

// ---------------- helpers ----------------
__device__ __forceinline__ uint32_t cvt_tf32(float f) {
    uint32_t r;
    asm("cvt.rna.tf32.f32 %0, %1;" : "=r"(r) : "f"(f));
    return r;
}

__device__ __forceinline__ void mma_tf32(float* c, const uint32_t* a, const uint32_t* b) {
    asm volatile(
        "mma.sync.aligned.m16n8k8.row.col.f32.tf32.tf32.f32 "
        "{%0,%1,%2,%3}, {%4,%5,%6,%7}, {%8,%9}, {%0,%1,%2,%3};"
        : "+f"(c[0]), "+f"(c[1]), "+f"(c[2]), "+f"(c[3])
        : "r"(a[0]), "r"(a[1]), "r"(a[2]), "r"(a[3]), "r"(b[0]), "r"(b[1]));
}

// ---------------- CSR build ----------------
__global__ void zero_kernel(int n) {
    int i = blockIdx.x * blockDim.x + threadIdx.x;
    if (i < n) { g_cnt_in[i] = 0; g_cnt_out[i] = 0; }
}

__global__ void hist_kernel(const int* __restrict__ ei, int E) {
    int e = blockIdx.x * blockDim.x + threadIdx.x;
    if (e < E) {
        atomicAdd(&g_cnt_out[ei[e]], 1);      // src -> out-degree (normalization)
        atomicAdd(&g_cnt_in[ei[E + e]], 1);   // dst -> in-degree (CSR)
    }
}

__global__ void scan_block_kernel(int n) {
    __shared__ int sm[1024];
    int t = threadIdx.x;
    int gid = blockIdx.x * 1024 + t;
    int v = (gid < n) ? g_cnt_in[gid] : 0;
    sm[t] = v;
    __syncthreads();
    #pragma unroll
    for (int off = 1; off < 1024; off <<= 1) {
        int add = (t >= off) ? sm[t - off] : 0;
        __syncthreads();
        sm[t] += add;
        __syncthreads();
    }
    if (gid < n) g_rowstart[gid] = sm[t] - v;  // exclusive within block
    if (t == 1023) g_bsum[blockIdx.x] = sm[1023];
}

// parallel exclusive scan over up to 1024 block sums (single block)
__global__ void scan_sums_kernel(int nb) {
    __shared__ int sm[1024];
    int t = threadIdx.x;
    int v = (t < nb) ? g_bsum[t] : 0;
    sm[t] = v;
    __syncthreads();
    #pragma unroll
    for (int off = 1; off < 1024; off <<= 1) {
        int add = (t >= off) ? sm[t - off] : 0;
        __syncthreads();
        sm[t] += add;
        __syncthreads();
    }
    if (t < nb) g_bsum[t] = sm[t] - v;  // exclusive
}

__global__ void scan_finish_kernel(int n) {
    int i = blockIdx.x * 1024 + threadIdx.x;
    if (i < n) {
        int v = g_rowstart[i] + g_bsum[blockIdx.x];
        g_rowstart[i] = v;
        g_cursor[i] = v;
        int d = g_cnt_out[i];
        g_dinv[i] = 1.0f / (float)(d > 1 ? d : 1);
    }
}

__global__ void scatter_kernel(const int* __restrict__ ei, int E) {
    int e = blockIdx.x * blockDim.x + threadIdx.x;
    if (e < E) {
        int d = ei[E + e];
        int pos = atomicAdd(&g_cursor[d], 1);
        g_csr[pos] = ei[e];  // source ids grouped by dst
    }
}

// ---------------- tf32 mma.sync GEMM (persistent) ----------------
// out[M,N_] = (A[M,128] @ W[128,N_]) * dinv[row]
//
// smem A layout: As[row][pos], row stride SA=136 uint32, pos(k) = (k>>3)*8 + (k&3)*2 + ((k>>2)&1)
//   -> fragment loads (a0,a2) and (a1,a3) are v2, conflict-free.
// smem B layout: Bs[(kblk*N_ + n)*8 + (k&3)*2 + ((k>>2)&1)]
//   -> fragment load (b0,b1) is v2, conflict-free.
#define SA 136

template <int N_, bool FIRST>
__global__ __launch_bounds__(256, 1)
void gemm_mma_kernel(const float* __restrict__ Ain, const float* __restrict__ W,
                     int M, int n_tiles) {
    extern __shared__ uint32_t smem[];
    uint32_t* As = smem;                  // 128 * SA
    uint32_t* Bs = smem + 128 * SA;       // 16 * N_ * 8 = 128*N_

    const float* __restrict__ A = FIRST ? Ain : g_hr;
    float* __restrict__ out = FIRST ? g_h1 : g_h2;

    constexpr int NT = N_ / 8;            // n-tiles per warp (16 or 8)
    const int tid = threadIdx.x;
    const int wid = tid >> 5;
    const int lane = tid & 31;
    const int qr = lane >> 2;             // 0..7
    const int qc = lane & 3;              // 0..3

    // ---- stage B = W [128, N_] once, tf32, permuted ----
    for (int idx = tid; idx < 128 * N_; idx += 256) {
        int k = idx / N_;
        int n = idx - k * N_;
        uint32_t v = cvt_tf32(W[idx]);
        Bs[(((k >> 3) * N_ + n) << 3) + ((k & 3) << 1) + ((k >> 2) & 1)] = v;
    }
    __syncthreads();

    const int wrow = wid * 16;            // warp's row offset within tile

    for (int t = blockIdx.x; t < n_tiles; t += gridDim.x) {
        const int row0 = t * 128;

        // ---- stage A tile [128 x 128] tf32, permuted ----
        #pragma unroll
        for (int it = 0; it < 16; it++) {
            int idx = tid + it * 256;      // float4 index, 4096 total
            int r = idx >> 5;
            int q = idx & 31;              // float4 within row, covers k = q*4..q*4+3
            int gr = row0 + r;
            float4 v = make_float4(0.f, 0.f, 0.f, 0.f);
            if (gr < M) v = *(const float4*)(A + (size_t)gr * 128 + q * 4);
            int kb = q >> 1;               // k block of 8
            int kh = q & 1;                // half within block
            uint32_t* dst = As + r * SA + kb * 8 + kh;
            dst[0] = cvt_tf32(v.x);
            dst[2] = cvt_tf32(v.y);
            dst[4] = cvt_tf32(v.z);
            dst[6] = cvt_tf32(v.w);
        }
        __syncthreads();

        // ---- compute: 16 k-steps, NT n-tiles ----
        float acc[NT][4];
        #pragma unroll
        for (int nt = 0; nt < NT; nt++)
            #pragma unroll
            for (int j = 0; j < 4; j++) acc[nt][j] = 0.f;

        #pragma unroll
        for (int s = 0; s < 16; s++) {
            uint32_t a[4];
            {
                const uint32_t* pa = As + (wrow + qr) * SA + s * 8 + qc * 2;
                uint2 lo = *(const uint2*)pa;
                uint2 hi = *(const uint2*)(pa + 8 * SA);
                a[0] = lo.x; a[1] = hi.x; a[2] = lo.y; a[3] = hi.y;
            }
            const uint32_t* pb = Bs + ((s * N_ + qr) << 3) + qc * 2;
            #pragma unroll
            for (int nt = 0; nt < NT; nt++) {
                uint2 bb = *(const uint2*)(pb + (nt << 6));
                uint32_t b[2] = {bb.x, bb.y};
                mma_tf32(acc[nt], a, b);
            }
        }
        __syncthreads();   // smem reuse next iteration

        // ---- epilogue: scale by dinv, store ----
        const int r0 = row0 + wrow + qr;
        const int r1 = r0 + 8;
        const float s0 = (r0 < M) ? g_dinv[r0] : 0.f;
        const float s1 = (r1 < M) ? g_dinv[r1] : 0.f;
        #pragma unroll
        for (int nt = 0; nt < NT; nt++) {
            int c = nt * 8 + qc * 2;
            if (r0 < M) {
                float2 v = make_float2(acc[nt][0] * s0, acc[nt][1] * s0);
                *(float2*)(out + (size_t)r0 * N_ + c) = v;
            }
            if (r1 < M) {
                float2 v = make_float2(acc[nt][2] * s1, acc[nt][3] * s1);
                *(float2*)(out + (size_t)r1 * N_ + c) = v;
            }
        }
    }
}

// ---------------- aggregation: warp per dst node, CSR gather-sum ----------------
template <int C, bool FIRST>
__global__ void agg_kernel(const float* __restrict__ bias, float* __restrict__ outp, int n) {
    int gw = (blockIdx.x * blockDim.x + threadIdx.x) >> 5;
    int lane = threadIdx.x & 31;
    if (gw >= n) return;

    const float* __restrict__ h = FIRST ? g_h1 : g_h2;
    float* __restrict__ out = FIRST ? g_hr : outp;

    int beg = g_rowstart[gw];
    int m = g_cnt_in[gw];

    if constexpr (C == 128) {
        size_t off = (size_t)lane * 4;
        float4 acc = make_float4(0.f, 0.f, 0.f, 0.f);
        int e = 0;
        for (; e + 2 <= m; e += 2) {
            int s0 = g_csr[beg + e];
            int s1 = g_csr[beg + e + 1];
            float4 a = *(const float4*)(h + (size_t)s0 * C + off);
            float4 b = *(const float4*)(h + (size_t)s1 * C + off);
            acc.x += a.x + b.x; acc.y += a.y + b.y;
            acc.z += a.z + b.z; acc.w += a.w + b.w;
        }
        if (e < m) {
            int s = g_csr[beg + e];
            float4 a = *(const float4*)(h + (size_t)s * C + off);
            acc.x += a.x; acc.y += a.y; acc.z += a.z; acc.w += a.w;
        }
        float4 bb = *(const float4*)(bias + lane * 4);
        acc.x += bb.x; acc.y += bb.y; acc.z += bb.z; acc.w += bb.w;
        if (FIRST) {
            acc.x = fmaxf(acc.x, 0.f); acc.y = fmaxf(acc.y, 0.f);
            acc.z = fmaxf(acc.z, 0.f); acc.w = fmaxf(acc.w, 0.f);
        }
        *(float4*)(out + (size_t)gw * C + off) = acc;
    } else {
        size_t off = (size_t)lane * 2;
        float2 acc = make_float2(0.f, 0.f);
        int e = 0;
        for (; e + 2 <= m; e += 2) {
            int s0 = g_csr[beg + e];
            int s1 = g_csr[beg + e + 1];
            float2 a = *(const float2*)(h + (size_t)s0 * C + off);
            float2 b = *(const float2*)(h + (size_t)s1 * C + off);
            acc.x += a.x + b.x; acc.y += a.y + b.y;
        }
        if (e < m) {
            int s = g_csr[beg + e];
            float2 a = *(const float2*)(h + (size_t)s * C + off);
            acc.x += a.x; acc.y += a.y;
        }
        float2 bb = *(const float2*)(bias + lane * 2);
        acc.x += bb.x; acc.y += bb.y;
        if (FIRST) { acc.x = fmaxf(acc.x, 0.f); acc.y = fmaxf(acc.y, 0.f); }
        *(float2*)(out + (size_t)gw * C + off) = acc;
    }
}

// ---------------- launch ----------------
extern "C" void kernel_launch(void* const* d_in, const int* in_sizes, int n_in,
                              void* d_out, int out_size) {
    const float* x  = (const float*)d_in[0];
    const int*   ei = (const int*)d_in[1];
    const float* W1 = (const float*)d_in[2];
    const float* b1 = (const float*)d_in[3];
    const float* W2 = (const float*)d_in[4];
    const float* b2 = (const float*)d_in[5];
    float* out = (float*)d_out;

    int N = in_sizes[0] / INC;   // 100000
    int E = in_sizes[1] / 2;     // 1600000

    int nb1k = (N + 1023) / 1024;
    int n_tiles = (N + 127) / 128;

    int sm_count = 148;
    {
        int dev = 0;
        if (cudaGetDevice(&dev) == cudaSuccess) {
            int c = 0;
            if (cudaDeviceGetAttribute(&c, cudaDevAttrMultiProcessorCount, dev) == cudaSuccess && c > 0)
                sm_count = c;
        }
    }
    int grid1 = n_tiles < sm_count ? n_tiles : sm_count;

    const int SMEM1 = (128 * SA + 128 * HIDC) * 4;   // A 69.6KB + B 64KB
    const int SMEM2 = (128 * SA + 128 * OUTC) * 4;   // A 69.6KB + B 32KB
    static bool attr_done = false;
    if (!attr_done) {
        cudaFuncSetAttribute(gemm_mma_kernel<HIDC, true>,
                             cudaFuncAttributeMaxDynamicSharedMemorySize, SMEM1);
        cudaFuncSetAttribute(gemm_mma_kernel<OUTC, false>,
                             cudaFuncAttributeMaxDynamicSharedMemorySize, SMEM2);
        attr_done = true;
    }

    zero_kernel<<<(N + 255) / 256, 256>>>(N);
    hist_kernel<<<(E + 255) / 256, 256>>>(ei, E);
    scan_block_kernel<<<nb1k, 1024>>>(N);
    scan_sums_kernel<<<1, 1024>>>(nb1k);
    scan_finish_kernel<<<nb1k, 1024>>>(N);
    scatter_kernel<<<(E + 255) / 256, 256>>>(ei, E);

    // layer 1
    gemm_mma_kernel<HIDC, true><<<grid1, 256, SMEM1>>>(x, W1, N, n_tiles);
    agg_kernel<HIDC, true><<<(N * 32 + 255) / 256, 256>>>(b1, nullptr, N);

    // layer 2
    gemm_mma_kernel<OUTC, false><<<grid1, 256, SMEM2>>>(nullptr, W2, N, n_tiles);
    agg_kernel<OUTC, false><<<(N * 32 + 255) / 256, 256>>>(b2, out, N);
}